// round 3
// baseline (speedup 1.0000x reference)
#include <cuda_runtime.h>

// PhotonicMesh: 512-port Clements mesh, 512 layers, 1024 batch rows.
// R3: packed fp32x2 math (fma.rn.f32x2 / FFMA2 via inline PTX).
// Lane t of a warp owns ports [16t,16t+16) of one row, stored as
//   R[m] = (re port 16t+m, re port 16t+m+8), I[m] likewise, m=0..7.
// This pairing makes even AND odd Clements layers pure 2-wide SIMD over
// butterflies (no swaps): even groups (R[2m],R[2m+1]); odd groups
// (R[2m+1],R[2m+2]) m=0..2 plus a leftover group pairing (7,8)&(15,16)
// which is exactly (R[7]) vs (R[0].hi, next-lane R[0].lo).
// Coefficients precomputed packed+pre-negated in 3 coalesced float4 arrays.

#define N_PORT  512
#define N_LAYER 512
#define ATTEN_F 0.97723722095581054f   // sqrt(10^(-0.2/10))

// Packed coefficient tables. Entry index: (l*4 + m)*32 + lane.
// Entry (l,m,lane) packs pairs pA = 8*lane+m (lo) and pB = pA+4 (hi).
//   g_c0 = (ctA, ctB, stA, stB)
//   g_c1 = (-stA, -stB, cosphiA, cosphiB)
//   g_c2 = (sinphiA, sinphiB, -sinphiA, -sinphiB)
__device__ float4 g_c0[N_LAYER * 128];
__device__ float4 g_c1[N_LAYER * 128];
__device__ float4 g_c2[N_LAYER * 128];

__global__ void pm_coef_kernel(const float* __restrict__ thetas,
                               const float* __restrict__ phis,
                               const int*   __restrict__ mzi_idx) {
    int l    = blockIdx.x;
    int lane = threadIdx.x & 31;
    int m    = threadIdx.x >> 5;          // 0..3
    int pA = 8 * lane + m;
    int pB = pA + 4;
    bool odd = (l & 1) != 0;

    float ct[2] = {1.f, 1.f}, st[2] = {0.f, 0.f};
    float cp[2] = {1.f, 1.f}, sp[2] = {0.f, 0.f};
    int p[2] = {pA, pB};
    #pragma unroll
    for (int h = 0; h < 2; h++) {
        bool valid = (!odd) || (p[h] < 255);   // odd layers: 255 pairs
        if (valid) {
            int u = odd ? (2 * p[h] + 1) : (2 * p[h]);  // upper port
            int mi = mzi_idx[l * N_PORT + u];
            float s_, c_;
            sincosf(thetas[mi], &s_, &c_);
            ct[h] = c_ * ATTEN_F;  st[h] = s_ * ATTEN_F;
            sincosf(phis[mi], &s_, &c_);
            cp[h] = c_;  sp[h] = s_;
        }
    }
    int idx = (l * 4 + m) * 32 + lane;
    g_c0[idx] = make_float4(ct[0], ct[1], st[0], st[1]);
    g_c1[idx] = make_float4(-st[0], -st[1], cp[0], cp[1]);
    g_c2[idx] = make_float4(sp[0], sp[1], -sp[0], -sp[1]);
}

// ---- packed fp32x2 primitives (FFMA2/FMUL2 via PTX) ----
__device__ __forceinline__ float2 mul2(float2 a, float2 b) {
    float2 d;
    asm("{\n\t.reg .b64 A,B,D;\n\t"
        "mov.b64 A,{%2,%3};\n\tmov.b64 B,{%4,%5};\n\t"
        "mul.rn.f32x2 D,A,B;\n\t"
        "mov.b64 {%0,%1},D;\n\t}"
        : "=f"(d.x), "=f"(d.y)
        : "f"(a.x), "f"(a.y), "f"(b.x), "f"(b.y));
    return d;
}
__device__ __forceinline__ float2 fma2(float2 a, float2 b, float2 c) {
    float2 d;
    asm("{\n\t.reg .b64 A,B,C,D;\n\t"
        "mov.b64 A,{%2,%3};\n\tmov.b64 B,{%4,%5};\n\tmov.b64 C,{%6,%7};\n\t"
        "fma.rn.f32x2 D,A,B,C;\n\t"
        "mov.b64 {%0,%1},D;\n\t}"
        : "=f"(d.x), "=f"(d.y)
        : "f"(a.x), "f"(a.y), "f"(b.x), "f"(b.y), "f"(c.x), "f"(c.y));
    return d;
}

struct Grp { float2 ct, st, nst, er, ei, nei; };

__device__ __forceinline__ void load_layer(Grp g[4], int l, int lane) {
    #pragma unroll
    for (int m = 0; m < 4; m++) {
        int idx = (l * 4 + m) * 32 + lane;
        float4 q0 = __ldg(&g_c0[idx]);
        float4 q1 = __ldg(&g_c1[idx]);
        float4 q2 = __ldg(&g_c2[idx]);
        g[m].ct  = make_float2(q0.x, q0.y);
        g[m].st  = make_float2(q0.z, q0.w);
        g[m].nst = make_float2(q1.x, q1.y);
        g[m].er  = make_float2(q1.z, q1.w);
        g[m].ei  = make_float2(q2.x, q2.y);
        g[m].nei = make_float2(q2.z, q2.w);
    }
}

// Packed butterfly on two independent MZIs:
//   u = ct*xi + st*xj ; xj' = ct*xj - st*xi ; xi' = e^{i phi} * u
__device__ __forceinline__ void bfly2(float2& Rxi, float2& Ixi,
                                      float2& Rxj, float2& Ixj,
                                      const Grp& c) {
    float2 ur = fma2(c.ct, Rxi, mul2(c.st, Rxj));
    float2 ui = fma2(c.ct, Ixi, mul2(c.st, Ixj));
    float2 vr = fma2(c.ct, Rxj, mul2(c.nst, Rxi));
    float2 vi = fma2(c.ct, Ixj, mul2(c.nst, Ixi));
    Rxi = fma2(c.er, ur, mul2(c.nei, ui));
    Ixi = fma2(c.er, ui, mul2(c.ei, ur));
    Rxj = vr;  Ixj = vi;
}

__global__ __launch_bounds__(256, 1)
void pm_mesh_kernel(const float* __restrict__ x, float* __restrict__ out) {
    const int lane = threadIdx.x & 31;
    const int row  = blockIdx.x * (blockDim.x >> 5) + (threadIdx.x >> 5);

    float2 R[8], I[8];   // R[m] = (re port m, re port m+8) within lane's 16 ports

    // ---- load input (real), imag = 0, into interleaved packing ----
    const float4* x4 = reinterpret_cast<const float4*>(x);
    #pragma unroll
    for (int v = 0; v < 4; v++) {
        float4 q = x4[(size_t)row * (N_PORT / 4) + lane * 4 + v];
        float vals[4] = {q.x, q.y, q.z, q.w};
        #pragma unroll
        for (int e = 0; e < 4; e++) {
            int j = 4 * v + e;
            if (j < 8) { R[j].x = vals[e];     I[j].x = 0.f; }
            else       { R[j - 8].y = vals[e]; I[j - 8].y = 0.f; }
        }
    }

    Grp A[4], B[4];
    load_layer(A, 0, lane);

    #pragma unroll 1
    for (int l = 0; l < N_LAYER; l += 2) {
        // prefetch odd layer l+1 while computing even layer l
        load_layer(B, l + 1, lane);

        // ---- EVEN layer l: groups (R[2m], R[2m+1]) ----
        #pragma unroll
        for (int m = 0; m < 4; m++)
            bfly2(R[2 * m], I[2 * m], R[2 * m + 1], I[2 * m + 1], A[m]);

        // prefetch even layer l+2 while computing odd layer l+1
        int ln = (l + 2 < N_LAYER) ? (l + 2) : 0;
        load_layer(A, ln, lane);

        // ---- ODD layer l+1 ----
        // boundary shuffles (pre-update snapshots)
        float nx0r  = __shfl_down_sync(0xffffffffu, R[0].x, 1);  // next lane x0
        float nx0i  = __shfl_down_sync(0xffffffffu, I[0].x, 1);
        float px15r = __shfl_up_sync  (0xffffffffu, R[7].y, 1);  // prev lane x15
        float px15i = __shfl_up_sync  (0xffffffffu, I[7].y, 1);
        float ctp   = __shfl_up_sync  (0xffffffffu, B[3].ct.y, 1);
        float nstp  = __shfl_up_sync  (0xffffffffu, B[3].nst.y, 1);
        if (lane == 0) { ctp = 1.f; nstp = 0.f; }   // global port 0 passthrough

        // snapshots for leftover group (old x8 and old x7)
        float2 xjr   = make_float2(R[0].y, nx0r);     // (x8, next x0)
        float2 xji   = make_float2(I[0].y, nx0i);
        float2 lowbr = make_float2(px15r, R[7].x);    // (prev x15, x7)
        float2 lowbi = make_float2(px15i, I[7].x);

        // local groups: (R[2m+1], R[2m+2]) for m=0..2
        #pragma unroll
        for (int m = 0; m < 3; m++)
            bfly2(R[2 * m + 1], I[2 * m + 1], R[2 * m + 2], I[2 * m + 2], B[m]);

        // leftover upper ports (x7, x15): phase applies; lane31 hi = identity coef
        {
            float2 ur = fma2(B[3].ct, R[7], mul2(B[3].st, xjr));
            float2 ui = fma2(B[3].ct, I[7], mul2(B[3].st, xji));
            R[7] = fma2(B[3].er, ur, mul2(B[3].nei, ui));
            I[7] = fma2(B[3].er, ui, mul2(B[3].ei, ur));
        }
        // leftover lower ports (x0, x8): real coefficients
        {
            float2 ct2l  = make_float2(ctp,  B[3].ct.x);
            float2 nst2l = make_float2(nstp, B[3].nst.x);
            R[0] = fma2(ct2l, R[0], mul2(nst2l, lowbr));
            I[0] = fma2(ct2l, I[0], mul2(nst2l, lowbi));
        }
    }

    // ---- square-law detection + store ----
    float4* o4 = reinterpret_cast<float4*>(out);
    #pragma unroll
    for (int v = 0; v < 4; v++) {
        float4 q;
        float vals[4];
        #pragma unroll
        for (int e = 0; e < 4; e++) {
            int j = 4 * v + e;
            vals[e] = (j < 8) ? (R[j].x * R[j].x + I[j].x * I[j].x)
                              : (R[j - 8].y * R[j - 8].y + I[j - 8].y * I[j - 8].y);
        }
        q.x = vals[0]; q.y = vals[1]; q.z = vals[2]; q.w = vals[3];
        o4[(size_t)row * (N_PORT / 4) + lane * 4 + v] = q;
    }
}

extern "C" void kernel_launch(void* const* d_in, const int* in_sizes, int n_in,
                              void* d_out, int out_size) {
    const float* x       = (const float*)d_in[0];
    const float* thetas  = (const float*)d_in[1];
    const float* phis    = (const float*)d_in[2];
    // d_in[3] = partner (unused: structure is static)
    const int*   mzi_idx = (const int*)d_in[4];
    // d_in[5] = role (unused: structure is static)
    float* out = (float*)d_out;

    pm_coef_kernel<<<N_LAYER, 128>>>(thetas, phis, mzi_idx);
    // 1024 warps: warp w handles row w; 128 CTAs x 8 warps = one full wave
    pm_mesh_kernel<<<128, 256>>>(x, out);
}

// round 4
// speedup vs baseline: 1.0184x; 1.0184x over previous
#include <cuda_runtime.h>

// PhotonicMesh: 512-port Clements mesh, 512 layers, 1024 batch rows.
// R4: packed fp32x2 (FFMA2) with NATIVE 64-bit register representation.
// State and coefficients live as unsigned long long (float pairs); all packed
// ops are single-instruction inline PTX with "l" constraints => no mov.b64
// pack/unpack inside the hot loop (R3's failure mode).
// Lane t owns ports [16t,16t+16) of one row, stored as
//   R[m] = pack(re port 16t+m, re port 16t+m+8), I[m] likewise, m=0..7.
// Even layers: groups (R[2m],R[2m+1]). Odd layers: groups (R[2m+1],R[2m+2])
// m=0..2 plus leftover pairing (7,8)&(15,16) handled with 6 shuffles/layer.

#define N_PORT  512
#define N_LAYER 512
#define ATTEN_F 0.97723722095581054f   // sqrt(10^(-0.2/10))

typedef unsigned long long u64;

// Packed coefficient tables. Entry index: (l*4 + m)*32 + lane.
// Entry (l,m,lane) packs pairs pA = 8*lane+m (lo) and pB = pA+4 (hi).
//   g_t0 = { (ctA,ctB),   (stA,stB)   }
//   g_t1 = { (-stA,-stB), (cpA,cpB)   }
//   g_t2 = { (spA,spB),   (-spA,-spB) }
__device__ ulonglong2 g_t0[N_LAYER * 128];
__device__ ulonglong2 g_t1[N_LAYER * 128];
__device__ ulonglong2 g_t2[N_LAYER * 128];

__device__ __forceinline__ u64 pk(float lo, float hi) {
    u64 d; asm("mov.b64 %0, {%1, %2};" : "=l"(d) : "f"(lo), "f"(hi)); return d;
}
__device__ __forceinline__ void upk(u64 v, float& lo, float& hi) {
    asm("mov.b64 {%0, %1}, %2;" : "=f"(lo), "=f"(hi) : "l"(v));
}
__device__ __forceinline__ u64 fma2(u64 a, u64 b, u64 c) {
    u64 d; asm("fma.rn.f32x2 %0, %1, %2, %3;" : "=l"(d) : "l"(a), "l"(b), "l"(c));
    return d;
}
__device__ __forceinline__ u64 mul2(u64 a, u64 b) {
    u64 d; asm("mul.rn.f32x2 %0, %1, %2;" : "=l"(d) : "l"(a), "l"(b));
    return d;
}

__global__ void pm_coef_kernel(const float* __restrict__ thetas,
                               const float* __restrict__ phis,
                               const int*   __restrict__ mzi_idx) {
    int l    = blockIdx.x;
    int lane = threadIdx.x & 31;
    int m    = threadIdx.x >> 5;          // 0..3
    int pA = 8 * lane + m;
    int pB = pA + 4;
    bool odd = (l & 1) != 0;

    float ct[2] = {1.f, 1.f}, st[2] = {0.f, 0.f};
    float cp[2] = {1.f, 1.f}, sp[2] = {0.f, 0.f};
    int p[2] = {pA, pB};
    #pragma unroll
    for (int h = 0; h < 2; h++) {
        bool valid = (!odd) || (p[h] < 255);   // odd layers: 255 pairs
        if (valid) {
            int u = odd ? (2 * p[h] + 1) : (2 * p[h]);  // upper port
            int mi = mzi_idx[l * N_PORT + u];
            float s_, c_;
            sincosf(thetas[mi], &s_, &c_);
            ct[h] = c_ * ATTEN_F;  st[h] = s_ * ATTEN_F;
            sincosf(phis[mi], &s_, &c_);
            cp[h] = c_;  sp[h] = s_;
        }
    }
    int idx = (l * 4 + m) * 32 + lane;
    g_t0[idx] = make_ulonglong2(pk(ct[0], ct[1]),  pk(st[0], st[1]));
    g_t1[idx] = make_ulonglong2(pk(-st[0], -st[1]), pk(cp[0], cp[1]));
    g_t2[idx] = make_ulonglong2(pk(sp[0], sp[1]),  pk(-sp[0], -sp[1]));
}

struct Grp { u64 ct, st, nst, er, ei, nei; };

__device__ __forceinline__ void load_layer(Grp g[4], int l, int lane) {
    #pragma unroll
    for (int m = 0; m < 4; m++) {
        int idx = (l * 4 + m) * 32 + lane;
        ulonglong2 q0 = __ldg(&g_t0[idx]);
        ulonglong2 q1 = __ldg(&g_t1[idx]);
        ulonglong2 q2 = __ldg(&g_t2[idx]);
        g[m].ct  = q0.x;  g[m].st  = q0.y;
        g[m].nst = q1.x;  g[m].er  = q1.y;
        g[m].ei  = q2.x;  g[m].nei = q2.y;
    }
}

// Packed butterfly on two independent MZIs:
//   u = ct*xi + st*xj ; xj' = ct*xj - st*xi ; xi' = e^{i phi} * u
__device__ __forceinline__ void bfly2(u64& Rxi, u64& Ixi,
                                      u64& Rxj, u64& Ixj,
                                      const Grp& c) {
    u64 ur = fma2(c.ct, Rxi, mul2(c.st, Rxj));
    u64 ui = fma2(c.ct, Ixi, mul2(c.st, Ixj));
    u64 vr = fma2(c.ct, Rxj, mul2(c.nst, Rxi));
    u64 vi = fma2(c.ct, Ixj, mul2(c.nst, Ixi));
    Rxi = fma2(c.er, ur, mul2(c.nei, ui));
    Ixi = fma2(c.er, ui, mul2(c.ei, ur));
    Rxj = vr;  Ixj = vi;
}

__global__ __launch_bounds__(256, 1)
void pm_mesh_kernel(const float* __restrict__ x, float* __restrict__ out) {
    const int lane = threadIdx.x & 31;
    const int row  = blockIdx.x * (blockDim.x >> 5) + (threadIdx.x >> 5);

    u64 R[8], I[8];   // R[m] = (re port m, re port m+8) within lane's 16 ports

    // ---- load input (real), imag = 0, into interleaved packing ----
    {
        const float4* x4 = reinterpret_cast<const float4*>(x);
        float t[16];
        #pragma unroll
        for (int v = 0; v < 4; v++) {
            float4 q = x4[(size_t)row * (N_PORT / 4) + lane * 4 + v];
            t[4 * v + 0] = q.x; t[4 * v + 1] = q.y;
            t[4 * v + 2] = q.z; t[4 * v + 3] = q.w;
        }
        #pragma unroll
        for (int m = 0; m < 8; m++) { R[m] = pk(t[m], t[m + 8]); I[m] = 0ull; }
    }

    Grp A[4], B[4];
    load_layer(A, 0, lane);

    #pragma unroll 1
    for (int l = 0; l < N_LAYER; l += 2) {
        // prefetch odd layer l+1 while computing even layer l
        load_layer(B, l + 1, lane);

        // ---- EVEN layer l: groups (R[2m], R[2m+1]) ----
        #pragma unroll
        for (int m = 0; m < 4; m++)
            bfly2(R[2 * m], I[2 * m], R[2 * m + 1], I[2 * m + 1], A[m]);

        // prefetch even layer l+2 while computing odd layer l+1
        int ln = (l + 2 < N_LAYER) ? (l + 2) : 0;
        load_layer(A, ln, lane);

        // ---- ODD layer l+1 ----
        // boundary extraction + shuffles (pre-update snapshots)
        float x0r, x8r, x0i, x8i, x7r, x15r, x7i, x15i;
        upk(R[0], x0r, x8r);  upk(I[0], x0i, x8i);
        upk(R[7], x7r, x15r); upk(I[7], x7i, x15i);
        float nx0r  = __shfl_down_sync(0xffffffffu, x0r, 1);   // next lane x0
        float nx0i  = __shfl_down_sync(0xffffffffu, x0i, 1);
        float px15r = __shfl_up_sync  (0xffffffffu, x15r, 1);  // prev lane x15
        float px15i = __shfl_up_sync  (0xffffffffu, x15i, 1);
        float ct3lo, ct3hi, nst3lo, nst3hi;
        upk(B[3].ct,  ct3lo,  ct3hi);
        upk(B[3].nst, nst3lo, nst3hi);
        float ctp  = __shfl_up_sync(0xffffffffu, ct3hi, 1);
        float nstp = __shfl_up_sync(0xffffffffu, nst3hi, 1);
        if (lane == 0) { ctp = 1.f; nstp = 0.f; }   // global port 0 passthrough

        u64 xjr   = pk(x8r,  nx0r);   // (x8, next x0)
        u64 xji   = pk(x8i,  nx0i);
        u64 lowbr = pk(px15r, x7r);   // (prev x15, x7)
        u64 lowbi = pk(px15i, x7i);
        u64 ct2l  = pk(ctp,  ct3lo);
        u64 nst2l = pk(nstp, nst3lo);

        // local groups: (R[2m+1], R[2m+2]) for m=0..2
        #pragma unroll
        for (int m = 0; m < 3; m++)
            bfly2(R[2 * m + 1], I[2 * m + 1], R[2 * m + 2], I[2 * m + 2], B[m]);

        // leftover upper ports (x7, x15): phase applies; lane31 hi = identity
        {
            u64 ur = fma2(B[3].ct, R[7], mul2(B[3].st, xjr));
            u64 ui = fma2(B[3].ct, I[7], mul2(B[3].st, xji));
            R[7] = fma2(B[3].er, ur, mul2(B[3].nei, ui));
            I[7] = fma2(B[3].er, ui, mul2(B[3].ei, ur));
        }
        // leftover lower ports (x0, x8): real coefficients
        R[0] = fma2(ct2l, R[0], mul2(nst2l, lowbr));
        I[0] = fma2(ct2l, I[0], mul2(nst2l, lowbi));
    }

    // ---- square-law detection + store ----
    {
        float pr[16];
        #pragma unroll
        for (int m = 0; m < 8; m++) {
            float rl, rh, il, ih;
            upk(R[m], rl, rh);  upk(I[m], il, ih);
            pr[m]     = rl * rl + il * il;
            pr[m + 8] = rh * rh + ih * ih;
        }
        float4* o4 = reinterpret_cast<float4*>(out);
        #pragma unroll
        for (int v = 0; v < 4; v++) {
            float4 q;
            q.x = pr[4 * v + 0]; q.y = pr[4 * v + 1];
            q.z = pr[4 * v + 2]; q.w = pr[4 * v + 3];
            o4[(size_t)row * (N_PORT / 4) + lane * 4 + v] = q;
        }
    }
}

extern "C" void kernel_launch(void* const* d_in, const int* in_sizes, int n_in,
                              void* d_out, int out_size) {
    const float* x       = (const float*)d_in[0];
    const float* thetas  = (const float*)d_in[1];
    const float* phis    = (const float*)d_in[2];
    // d_in[3] = partner (unused: structure is static)
    const int*   mzi_idx = (const int*)d_in[4];
    // d_in[5] = role (unused: structure is static)
    float* out = (float*)d_out;

    pm_coef_kernel<<<N_LAYER, 128>>>(thetas, phis, mzi_idx);
    // 1024 warps: warp w handles row w; 128 CTAs x 8 warps = one full wave
    pm_mesh_kernel<<<128, 256>>>(x, out);
}

// round 5
// speedup vs baseline: 1.0301x; 1.0115x over previous
#include <cuda_runtime.h>

// PhotonicMesh: 512-port Clements mesh, 512 layers, 1024 batch rows.
// R5: scalar fp32 butterflies (R2 math), but each row is split across a
// WARP PAIR (lane owns 8 ports) => 2048 warps = 256 CTAs x 256 threads
// = 4 warps/SMSP, doubling latency-hiding depth (R2-R4 were latency-bound
// at 2 warps/SMSP, issue ~21-33%).
// Warp-half h of a row owns ports [256h+8t, 256h+8t+8) at lane t.
// Even layers fully lane-local; odd layers: 3 local pairs + cross pair
// (s7, next s0): lane-internal via shuffle, warp-pair boundary (ports
// 255/256) via a 4-float smem slot + ONE __syncthreads per 2 layers.

#define N_PORT  512
#define N_LAYER 512
#define ATTEN_F 0.97723722095581054f   // sqrt(10^(-0.2/10))

// Coefficient table: entry [(l*4 + k)*64 + 32h + t] holds float4
// (ct*ATTEN, st*ATTEN, cos(phi), sin(phi)) for pair p = 128h + 4t + k of
// layer l (identity for invalid pairs). Warp reads 512B coalesced per k.
__device__ float4 g_tab[N_LAYER * 4 * 64];

__global__ void pm_coef_kernel(const float* __restrict__ thetas,
                               const float* __restrict__ phis,
                               const int*   __restrict__ mzi_idx) {
    int l   = blockIdx.x;
    int tid = threadIdx.x;            // 256
    int t = tid & 31;
    int h = (tid >> 5) & 1;
    int k = tid >> 6;                 // 0..3
    int p = 128 * h + 4 * t + k;
    bool odd = (l & 1) != 0;
    float4 c = make_float4(1.f, 0.f, 1.f, 0.f);   // identity
    bool valid = odd ? (p < 255) : true;          // odd layers: 255 pairs
    if (valid) {
        int u = odd ? (2 * p + 1) : (2 * p);      // upper port of pair
        int m = mzi_idx[l * N_PORT + u];
        float st, ct, sp, cp;
        sincosf(thetas[m], &st, &ct);
        sincosf(phis[m],   &sp, &cp);
        c = make_float4(ct * ATTEN_F, st * ATTEN_F, cp, sp);
    }
    g_tab[(l * 4 + k) * 64 + 32 * h + t] = c;
}

// new_i = e^{i phi}(ct*x_i + st*x_j) ; new_j = ct*x_j - st*x_i
__device__ __forceinline__ void butterfly(float2& xi, float2& xj, float4 c) {
    float ct = c.x, st = c.y, er = c.z, ei = c.w;
    float ur = ct * xi.x + st * xj.x;
    float ui = ct * xi.y + st * xj.y;
    float vr = ct * xj.x - st * xi.x;
    float vi = ct * xj.y - st * xi.y;
    xi.x = er * ur - ei * ui;
    xi.y = er * ui + ei * ur;
    xj.x = vr;
    xj.y = vi;
}

__global__ __launch_bounds__(256, 2)
void pm_mesh_kernel(const float* __restrict__ x, float* __restrict__ out) {
    // boundary exchange: [parity][rowInCta][h0s7.re, h0s7.im, h1s0.re, h1s0.im]
    __shared__ float buf[2][4][4];

    const int lane = threadIdx.x & 31;
    const int w    = threadIdx.x >> 5;    // 0..7
    const int rc   = w >> 1;              // row within CTA: 0..3
    const int h    = w & 1;               // warp-half: 0 = ports 0..255
    const int row  = blockIdx.x * 4 + rc;
    const int base = 32 * h + lane;       // coefficient lane index

    float2 s[8];   // lane owns ports 256h+8*lane .. +8

    // ---- load input (real), imag = 0 ----
    {
        const float4* x4 = reinterpret_cast<const float4*>(x);
        size_t off = (size_t)row * (N_PORT / 4) + h * 64 + lane * 2;
        float4 a0 = x4[off];
        float4 a1 = x4[off + 1];
        s[0] = make_float2(a0.x, 0.f); s[1] = make_float2(a0.y, 0.f);
        s[2] = make_float2(a0.z, 0.f); s[3] = make_float2(a0.w, 0.f);
        s[4] = make_float2(a1.x, 0.f); s[5] = make_float2(a1.y, 0.f);
        s[6] = make_float2(a1.z, 0.f); s[7] = make_float2(a1.w, 0.f);
    }

    float4 A[4], B[4], cx = make_float4(1.f, 0.f, 1.f, 0.f);
    #pragma unroll
    for (int k = 0; k < 4; k++) A[k] = __ldg(&g_tab[k * 64 + base]);

    #pragma unroll 1
    for (int l = 0; l < N_LAYER; l += 2) {
        // prefetch odd layer l+1
        #pragma unroll
        for (int k = 0; k < 4; k++)
            B[k] = __ldg(&g_tab[((l + 1) * 4 + k) * 64 + base]);
        // h1 lane0 also needs pair 127's coef (owned by h0 lane31, k=3)
        if (h == 1 && lane == 0)
            cx = __ldg(&g_tab[((l + 1) * 4 + 3) * 64 + 31]);

        // ---- EVEN layer l: pairs (s0,s1)(s2,s3)(s4,s5)(s6,s7), lane-local ----
        #pragma unroll
        for (int k = 0; k < 4; k++)
            butterfly(s[2 * k], s[2 * k + 1], A[k]);

        // publish warp-pair boundary values (pre-odd-layer snapshots)
        const int par = (l >> 1) & 1;
        if (h == 0 && lane == 31) { buf[par][rc][0] = s[7].x; buf[par][rc][1] = s[7].y; }
        if (h == 1 && lane == 0)  { buf[par][rc][2] = s[0].x; buf[par][rc][3] = s[0].y; }

        // prefetch even layer l+2 (in flight across the barrier)
        int ln = (l + 2 < N_LAYER) ? (l + 2) : 0;
        #pragma unroll
        for (int k = 0; k < 4; k++)
            A[k] = __ldg(&g_tab[(ln * 4 + k) * 64 + base]);

        __syncthreads();

        // ---- ODD layer l+1 ----
        // snapshots (pre-update)
        float nx0r = __shfl_down_sync(0xffffffffu, s[0].x, 1);  // next lane s0
        float nx0i = __shfl_down_sync(0xffffffffu, s[0].y, 1);
        float px7r = __shfl_up_sync  (0xffffffffu, s[7].x, 1);  // prev lane s7
        float px7i = __shfl_up_sync  (0xffffffffu, s[7].y, 1);
        float ctp  = __shfl_up_sync  (0xffffffffu, B[3].x, 1);  // prev cross coef
        float stp  = __shfl_up_sync  (0xffffffffu, B[3].y, 1);
        if (h == 0 && lane == 31) {                 // partner = port 256 (other warp)
            nx0r = buf[par][rc][2]; nx0i = buf[par][rc][3];
        }
        if (h == 1 && lane == 0) {                  // partner = port 255 (other warp)
            px7r = buf[par][rc][0]; px7i = buf[par][rc][1];
            ctp = cx.x; stp = cx.y;
        }
        if (h == 0 && lane == 0) { ctp = 1.f; stp = 0.f; }  // global port 0 pass

        // local pairs (s1,s2)(s3,s4)(s5,s6)
        butterfly(s[1], s[2], B[0]);
        butterfly(s[3], s[4], B[1]);
        butterfly(s[5], s[6], B[2]);

        // cross pair upper port (s7) with partner nx0; identity coef at port 511
        {
            float ct = B[3].x, st = B[3].y, er = B[3].z, ei = B[3].w;
            float ur = ct * s[7].x + st * nx0r;
            float ui = ct * s[7].y + st * nx0i;
            s[7].x = er * ur - ei * ui;
            s[7].y = er * ui + ei * ur;
        }
        // cross pair lower port (s0) with partner px7 (real coefficients)
        {
            float2 x0 = s[0];
            s[0].x = ctp * x0.x - stp * px7r;
            s[0].y = ctp * x0.y - stp * px7i;
        }
    }

    // ---- square-law detection + store ----
    {
        float4 o0, o1;
        o0.x = s[0].x * s[0].x + s[0].y * s[0].y;
        o0.y = s[1].x * s[1].x + s[1].y * s[1].y;
        o0.z = s[2].x * s[2].x + s[2].y * s[2].y;
        o0.w = s[3].x * s[3].x + s[3].y * s[3].y;
        o1.x = s[4].x * s[4].x + s[4].y * s[4].y;
        o1.y = s[5].x * s[5].x + s[5].y * s[5].y;
        o1.z = s[6].x * s[6].x + s[6].y * s[6].y;
        o1.w = s[7].x * s[7].x + s[7].y * s[7].y;
        float4* o4 = reinterpret_cast<float4*>(out);
        size_t off = (size_t)row * (N_PORT / 4) + h * 64 + lane * 2;
        o4[off]     = o0;
        o4[off + 1] = o1;
    }
}

extern "C" void kernel_launch(void* const* d_in, const int* in_sizes, int n_in,
                              void* d_out, int out_size) {
    const float* x       = (const float*)d_in[0];
    const float* thetas  = (const float*)d_in[1];
    const float* phis    = (const float*)d_in[2];
    // d_in[3] = partner (unused: structure is static)
    const int*   mzi_idx = (const int*)d_in[4];
    // d_in[5] = role (unused: structure is static)
    float* out = (float*)d_out;

    pm_coef_kernel<<<N_LAYER, 256>>>(thetas, phis, mzi_idx);
    // 2048 warps: 256 CTAs x 8 warps; warp pair (2r,2r+1) in a CTA = one row
    pm_mesh_kernel<<<256, 256>>>(x, out);
}